// round 2
// baseline (speedup 1.0000x reference)
#include <cuda_runtime.h>

#define A_ANG 192
#define DDET  576
#define W_IMG 384
#define TX 32
#define TY 12

// Scratch (device globals: allocation-free per harness rules)
__device__ float  g_img[W_IMG * W_IMG];          // backprojection of raw sino
__device__ float2 g_packed[A_ANG * DDET];        // (sino, sino_pred) interleaved

// ---------------------------------------------------------------------------
// Kernel 1: fused conv1 (1->16, 5x5, pad2) + conv2 (16->1, 5x5, pad2)
// Writes sino_pred to d_out[0:110592] and packed (sino, sino_pred) float2.
// Block = (32,12) threads, tile = 32x12 outputs. Static smem ~43KB.
// ---------------------------------------------------------------------------
__global__ void __launch_bounds__(TX* TY) conv12_kernel(
    const float* __restrict__ sino,
    const float* __restrict__ w1, const float* __restrict__ b1,
    const float* __restrict__ w2, const float* __restrict__ b2,
    float* __restrict__ sino_pred)
{
    __shared__ float s_sino[(TY + 8) * (TX + 8)];      // 20 x 40
    __shared__ float s_h[16][TY + 4][TX + 4];          // 16 x 16 x 36
    __shared__ float s_w1[400];
    __shared__ float s_w2[400];
    __shared__ float s_b1[16];
    __shared__ float s_b2;

    const int tid = threadIdx.y * TX + threadIdx.x;
    const int ox0 = blockIdx.x * TX;
    const int oy0 = blockIdx.y * TY;

    for (int i = tid; i < 400; i += TX * TY) { s_w1[i] = w1[i]; s_w2[i] = w2[i]; }
    if (tid < 16) s_b1[tid] = b1[tid];
    if (tid == 0) s_b2 = b2[0];

    // Load sino tile with halo 4 (origin ox0-4, oy0-4), zero-padded.
    for (int i = tid; i < (TY + 8) * (TX + 8); i += TX * TY) {
        int ly = i / (TX + 8), lx = i % (TX + 8);
        int gy = oy0 - 4 + ly, gx = ox0 - 4 + lx;
        float v = 0.0f;
        if (gy >= 0 && gy < A_ANG && gx >= 0 && gx < DDET)
            v = sino[gy * DDET + gx];
        s_sino[i] = v;
    }
    __syncthreads();

    // conv1: compute h on (TX+4)x(TY+4) positions, 16 channels each.
    // IMPORTANT: h positions whose GLOBAL coords fall outside the image must be
    // ZERO (conv2's zero-padding pads h itself, not a recomputed halo).
    for (int pos = tid; pos < (TX + 4) * (TY + 4); pos += TX * TY) {
        int hy = pos / (TX + 4), hx = pos % (TX + 4);
        int ghy = oy0 - 2 + hy, ghx = ox0 - 2 + hx;
        bool valid = (ghy >= 0) && (ghy < A_ANG) && (ghx >= 0) && (ghx < DDET);
        float acc[16];
        #pragma unroll
        for (int oc = 0; oc < 16; oc++) acc[oc] = s_b1[oc];
        #pragma unroll
        for (int ky = 0; ky < 5; ky++) {
            #pragma unroll
            for (int kx = 0; kx < 5; kx++) {
                float s = s_sino[(hy + ky) * (TX + 8) + hx + kx];
                int k = ky * 5 + kx;
                #pragma unroll
                for (int oc = 0; oc < 16; oc++)
                    acc[oc] = fmaf(s, s_w1[oc * 25 + k], acc[oc]);
            }
        }
        #pragma unroll
        for (int oc = 0; oc < 16; oc++)
            s_h[oc][hy][hx] = valid ? acc[oc] : 0.0f;
    }
    __syncthreads();

    // conv2: one output pixel per thread.
    const int tx = threadIdx.x, ty = threadIdx.y;
    float acc = s_b2;
    #pragma unroll
    for (int ic = 0; ic < 16; ic++) {
        #pragma unroll
        for (int ky = 0; ky < 5; ky++) {
            #pragma unroll
            for (int kx = 0; kx < 5; kx++)
                acc = fmaf(s_h[ic][ty + ky][tx + kx],
                           s_w2[ic * 25 + ky * 5 + kx], acc);
        }
    }
    const int gx = ox0 + tx, gy = oy0 + ty;      // exact grid: no bounds needed
    const int idx = gy * DDET + gx;
    sino_pred[idx] = acc;
    g_packed[idx] = make_float2(s_sino[(ty + 4) * (TX + 8) + tx + 4], acc);
}

// ---------------------------------------------------------------------------
// Kernel 2: dual fan-beam backprojection (sino -> g_img, sino_pred -> img_sino)
// Shared geometry: one s / i0 / frac per (pixel, angle); float2 gathers.
// ---------------------------------------------------------------------------
__global__ void __launch_bounds__(256) backproj_kernel(
    const float* __restrict__ angles,
    float* __restrict__ img_sino)
{
    __shared__ float s_cb[A_ANG], s_sb[A_ANG];
    const int tid = threadIdx.x;
    for (int i = tid; i < A_ANG; i += 256) {
        float sv, cv;
        sincosf(angles[i], &sv, &cv);
        s_cb[i] = cv; s_sb[i] = sv;
    }
    __syncthreads();

    const int p = blockIdx.x * 256 + tid;
    const int x = p % W_IMG, y = p / W_IMG;
    const float X = (float)x - 191.5f;
    const float Y = (float)y - 191.5f;

    float acc0 = 0.0f, acc1 = 0.0f;
    #pragma unroll 4
    for (int a = 0; a < A_ANG; a++) {
        const float cb = s_cb[a], sb = s_sb[a];
        const float px = cb * X + sb * Y;
        const float py = cb * Y - sb * X;
        const float s  = fmaf(px, 576.0f / (576.0f + py), 287.5f);
        const float i0f = floorf(s);
        const float frac = s - i0f;
        const int i0 = (int)i0f;
        const int i1 = i0 + 1;
        float2 v0 = make_float2(0.0f, 0.0f);
        float2 v1 = make_float2(0.0f, 0.0f);
        if ((unsigned)i0 < (unsigned)DDET) v0 = __ldg(&g_packed[a * DDET + i0]);
        if ((unsigned)i1 < (unsigned)DDET) v1 = __ldg(&g_packed[a * DDET + i1]);
        const float w0 = 1.0f - frac;
        acc0 = fmaf(v0.x, w0, acc0);
        acc0 = fmaf(v1.x, frac, acc0);
        acc1 = fmaf(v0.y, w0, acc1);
        acc1 = fmaf(v1.y, frac, acc1);
    }
    g_img[p] = acc0;
    img_sino[p] = acc1;
}

// ---------------------------------------------------------------------------
// Kernel 3: conv3 (2->1, 3x3, pad1) on concat([img, img_sino])
// ---------------------------------------------------------------------------
__global__ void __launch_bounds__(256) conv3_kernel(
    const float* __restrict__ w3, const float* __restrict__ b3,
    const float* __restrict__ img_sino,
    float* __restrict__ img_pred)
{
    __shared__ float s_w[18];
    __shared__ float s_b;
    if (threadIdx.x < 18) s_w[threadIdx.x] = w3[threadIdx.x];
    if (threadIdx.x == 0) s_b = b3[0];
    __syncthreads();

    const int p = blockIdx.x * 256 + threadIdx.x;
    const int x = p % W_IMG, y = p / W_IMG;
    float acc = s_b;
    #pragma unroll
    for (int ky = 0; ky < 3; ky++) {
        const int yy = y + ky - 1;
        if (yy < 0 || yy >= W_IMG) continue;
        #pragma unroll
        for (int kx = 0; kx < 3; kx++) {
            const int xx = x + kx - 1;
            if (xx < 0 || xx >= W_IMG) continue;
            const int q = yy * W_IMG + xx;
            acc = fmaf(g_img[q],    s_w[ky * 3 + kx],     acc);
            acc = fmaf(__ldg(&img_sino[q]), s_w[9 + ky * 3 + kx], acc);
        }
    }
    img_pred[p] = acc;
}

// ---------------------------------------------------------------------------
extern "C" void kernel_launch(void* const* d_in, const int* in_sizes, int n_in,
                              void* d_out, int out_size)
{
    const float* sino   = (const float*)d_in[0];
    const float* angles = (const float*)d_in[1];
    const float* w1     = (const float*)d_in[2];
    const float* b1     = (const float*)d_in[3];
    const float* w2     = (const float*)d_in[4];
    const float* b2     = (const float*)d_in[5];
    const float* w3     = (const float*)d_in[6];
    const float* b3     = (const float*)d_in[7];

    float* out       = (float*)d_out;
    float* sino_pred = out;                              // 192*576   = 110592
    float* img_sino  = out + A_ANG * DDET;               // 384*384   = 147456
    float* img_pred  = out + A_ANG * DDET + W_IMG * W_IMG;

    dim3 grid1(DDET / TX, A_ANG / TY);
    dim3 block1(TX, TY);
    conv12_kernel<<<grid1, block1>>>(sino, w1, b1, w2, b2, sino_pred);

    backproj_kernel<<<(W_IMG * W_IMG) / 256, 256>>>(angles, img_sino);

    conv3_kernel<<<(W_IMG * W_IMG) / 256, 256>>>(w3, b3, img_sino, img_pred);
}

// round 3
// speedup vs baseline: 2.0707x; 2.0707x over previous
#include <cuda_runtime.h>

#define A_ANG 192
#define DDET  576
#define W_IMG 384
#define PADW  1152
#define POFF  256

// Scratch (__device__ globals: allocation-free). g_pad is zero-initialized at
// module load; padding columns are never written, so they stay zero across
// all graph replays (out-of-range detector taps contribute exactly 0).
__device__ float2 g_pad[A_ANG * PADW];     // (sino, sino_pred) packed, padded
__device__ float  g_img[W_IMG * W_IMG];    // backprojection of raw sino
__device__ float  g_G[625];                // G[d][e] = sum_c w2[c,d]*w1[c,e]
__device__ float  g_B[25];                 // B[d]    = sum_c w2[c,d]*b1[c]
__device__ float  g_W[81];                 // interior 9x9 composite kernel
__device__ float  g_bias[1];               // b2 + sum_d B[d]

// ---------------------------------------------------------------------------
// Kernel 0: build composite-conv tables (1 block, trivial cost)
// ---------------------------------------------------------------------------
__global__ void __launch_bounds__(640) precompute_kernel(
    const float* __restrict__ w1, const float* __restrict__ b1,
    const float* __restrict__ w2, const float* __restrict__ b2)
{
    __shared__ float sG[625];
    const int tid = threadIdx.x;
    if (tid < 625) {
        int d = tid / 25, e = tid % 25;
        float g = 0.0f;
        #pragma unroll
        for (int c = 0; c < 16; c++) g = fmaf(w2[c * 25 + d], w1[c * 25 + e], g);
        sG[tid] = g;
        g_G[tid] = g;
    }
    if (tid < 25) {
        float s = 0.0f;
        #pragma unroll
        for (int c = 0; c < 16; c++) s = fmaf(w2[c * 25 + tid], b1[c], s);
        g_B[tid] = s;
    }
    __syncthreads();
    if (tid < 81) {
        int tty = tid / 9, ttx = tid % 9;
        float w = 0.0f;
        for (int dy = 0; dy < 5; dy++) {
            int ey = tty - dy; if (ey < 0 || ey > 4) continue;
            for (int dx = 0; dx < 5; dx++) {
                int ex = ttx - dx; if (ex < 0 || ex > 4) continue;
                w += sG[(dy * 5 + dx) * 25 + ey * 5 + ex];
            }
        }
        g_W[tid] = w;
    }
    if (tid == 0) {
        float bias = b2[0];
        #pragma unroll
        for (int c = 0; c < 16; c++) {
            float s2 = 0.0f;
            #pragma unroll
            for (int d = 0; d < 25; d++) s2 += w2[c * 25 + d];
            bias = fmaf(s2, b1[c], bias);
        }
        g_bias[0] = bias;
    }
}

// ---------------------------------------------------------------------------
// Kernel 1: composite conv (sino -> sino_pred), writes packed padded sinogram.
// Interior pixels: 9x9 kernel W (81 FMA). Border pixels: exact per-d formula.
// ---------------------------------------------------------------------------
#define CTX 32
#define CTY 8
__global__ void __launch_bounds__(CTX * CTY) conv12_kernel(
    const float* __restrict__ sino,
    const float* __restrict__ b2,
    float* __restrict__ sino_pred)
{
    __shared__ float t[CTY + 8][CTX + 8];   // 16 x 40, halo 4, zero-padded
    __shared__ float sW[81];
    __shared__ float sG[625];
    __shared__ float sB[25];
    __shared__ float sbias;

    const int tid = threadIdx.y * CTX + threadIdx.x;
    if (tid < 81) sW[tid] = g_W[tid];
    for (int i = tid; i < 625; i += CTX * CTY) sG[i] = g_G[i];
    if (tid < 25) sB[tid] = g_B[tid];
    if (tid == 255) sbias = g_bias[0];

    const int bx0 = blockIdx.x * CTX, by0 = blockIdx.y * CTY;
    for (int i = tid; i < (CTY + 8) * (CTX + 8); i += CTX * CTY) {
        int ly = i / (CTX + 8), lx = i % (CTX + 8);
        int gy = by0 - 4 + ly, gx = bx0 - 4 + lx;
        float v = 0.0f;
        if ((unsigned)gy < A_ANG && (unsigned)gx < DDET) v = sino[gy * DDET + gx];
        t[ly][lx] = v;
    }
    __syncthreads();

    const int tx = threadIdx.x, ty = threadIdx.y;
    const int gx = bx0 + tx, gy = by0 + ty;
    float acc;
    const bool interior = (gy >= 2) && (gy <= A_ANG - 3) && (gx >= 2) && (gx <= DDET - 3);
    if (interior) {
        acc = sbias;
        #pragma unroll
        for (int a = 0; a < 9; a++)
            #pragma unroll
            for (int b = 0; b < 9; b++)
                acc = fmaf(t[ty + a][tx + b], sW[a * 9 + b], acc);
    } else {
        acc = b2[0];
        for (int dy = 0; dy < 5; dy++) {
            int hy = gy + dy - 2; if ((unsigned)hy >= A_ANG) continue;
            for (int dx = 0; dx < 5; dx++) {
                int hx = gx + dx - 2; if ((unsigned)hx >= DDET) continue;
                float a2 = sB[dy * 5 + dx];
                #pragma unroll
                for (int ey = 0; ey < 5; ey++)
                    #pragma unroll
                    for (int ex = 0; ex < 5; ex++)
                        a2 = fmaf(t[ty + dy + ey][tx + dx + ex],
                                  sG[(dy * 5 + dx) * 25 + ey * 5 + ex], a2);
                acc += a2;
            }
        }
    }
    const int idx = gy * DDET + gx;
    sino_pred[idx] = acc;
    g_pad[gy * PADW + POFF + gx] = make_float2(t[ty + 4][tx + 4], acc);
}

// ---------------------------------------------------------------------------
// Kernel 2: dual fan-beam backprojection, 2 pixels/thread, no predication.
// ---------------------------------------------------------------------------
__global__ void __launch_bounds__(256) backproj_kernel(
    const float* __restrict__ angles,
    float* __restrict__ img_sino)
{
    __shared__ float s_cb[A_ANG], s_sb[A_ANG];
    const int tid = threadIdx.x;
    if (tid < A_ANG) {
        float sv, cv;
        sincosf(angles[tid], &sv, &cv);
        s_cb[tid] = cv; s_sb[tid] = sv;
    }
    __syncthreads();

    const int p = (blockIdx.x * 256 + tid) * 2;
    const int x = p % W_IMG, y = p / W_IMG;
    const float X0 = (float)x - 191.5f;
    const float X1 = X0 + 1.0f;
    const float Y  = (float)y - 191.5f;

    float a00 = 0.0f, a01 = 0.0f;   // pixel0: sino, sino_pred
    float a10 = 0.0f, a11 = 0.0f;   // pixel1
    #pragma unroll 2
    for (int a = 0; a < A_ANG; a++) {
        const float cb = s_cb[a], sb = s_sb[a];
        const float sbY = sb * Y, cbY = cb * Y;
        const float2* __restrict__ row = &g_pad[a * PADW + POFF];
        {
            const float px = fmaf(cb, X0, sbY);
            const float py = fmaf(-sb, X0, cbY);
            const float f  = __fdividef(576.0f, 576.0f + py);
            const float s  = fmaf(px, f, 287.5f);
            const int i0   = __float2int_rd(s);
            const float fr = s - (float)i0;
            const float2 v0 = row[i0];
            const float2 v1 = row[i0 + 1];
            const float w0 = 1.0f - fr;
            a00 = fmaf(v0.x, w0, a00); a00 = fmaf(v1.x, fr, a00);
            a01 = fmaf(v0.y, w0, a01); a01 = fmaf(v1.y, fr, a01);
        }
        {
            const float px = fmaf(cb, X1, sbY);
            const float py = fmaf(-sb, X1, cbY);
            const float f  = __fdividef(576.0f, 576.0f + py);
            const float s  = fmaf(px, f, 287.5f);
            const int i0   = __float2int_rd(s);
            const float fr = s - (float)i0;
            const float2 v0 = row[i0];
            const float2 v1 = row[i0 + 1];
            const float w0 = 1.0f - fr;
            a10 = fmaf(v0.x, w0, a10); a10 = fmaf(v1.x, fr, a10);
            a11 = fmaf(v0.y, w0, a11); a11 = fmaf(v1.y, fr, a11);
        }
    }
    g_img[p] = a00;     g_img[p + 1] = a10;
    img_sino[p] = a01;  img_sino[p + 1] = a11;
}

// ---------------------------------------------------------------------------
// Kernel 3: conv3 (2->1, 3x3, pad1) on concat([img, img_sino])
// ---------------------------------------------------------------------------
__global__ void __launch_bounds__(256) conv3_kernel(
    const float* __restrict__ w3, const float* __restrict__ b3,
    const float* __restrict__ img_sino,
    float* __restrict__ img_pred)
{
    __shared__ float s_w[18];
    __shared__ float s_b;
    if (threadIdx.x < 18) s_w[threadIdx.x] = w3[threadIdx.x];
    if (threadIdx.x == 0) s_b = b3[0];
    __syncthreads();

    const int p = blockIdx.x * 256 + threadIdx.x;
    const int x = p % W_IMG, y = p / W_IMG;
    float acc = s_b;
    #pragma unroll
    for (int ky = 0; ky < 3; ky++) {
        const int yy = y + ky - 1;
        if (yy < 0 || yy >= W_IMG) continue;
        #pragma unroll
        for (int kx = 0; kx < 3; kx++) {
            const int xx = x + kx - 1;
            if (xx < 0 || xx >= W_IMG) continue;
            const int q = yy * W_IMG + xx;
            acc = fmaf(g_img[q],            s_w[ky * 3 + kx],     acc);
            acc = fmaf(__ldg(&img_sino[q]), s_w[9 + ky * 3 + kx], acc);
        }
    }
    img_pred[p] = acc;
}

// ---------------------------------------------------------------------------
extern "C" void kernel_launch(void* const* d_in, const int* in_sizes, int n_in,
                              void* d_out, int out_size)
{
    const float* sino   = (const float*)d_in[0];
    const float* angles = (const float*)d_in[1];
    const float* w1     = (const float*)d_in[2];
    const float* b1     = (const float*)d_in[3];
    const float* w2     = (const float*)d_in[4];
    const float* b2     = (const float*)d_in[5];
    const float* w3     = (const float*)d_in[6];
    const float* b3     = (const float*)d_in[7];

    float* out       = (float*)d_out;
    float* sino_pred = out;                               // 192*576 = 110592
    float* img_sino  = out + A_ANG * DDET;                // 384*384 = 147456
    float* img_pred  = out + A_ANG * DDET + W_IMG * W_IMG;

    precompute_kernel<<<1, 640>>>(w1, b1, w2, b2);

    dim3 grid1(DDET / CTX, A_ANG / CTY);
    dim3 block1(CTX, CTY);
    conv12_kernel<<<grid1, block1>>>(sino, b2, sino_pred);

    backproj_kernel<<<(W_IMG * W_IMG) / 512, 256>>>(angles, img_sino);

    conv3_kernel<<<(W_IMG * W_IMG) / 256, 256>>>(w3, b3, img_sino, img_pred);
}